// round 4
// baseline (speedup 1.0000x reference)
#include <cuda_runtime.h>
#include <cstdint>

// Problem constants
#define TT   8
#define NN   100000
#define DD   128
#define EE   50000
#define HH0  64
#define HH1  32

// Scratch (allocation-free rule: __device__ globals)
__device__ float g_sim[EE * TT];   // s1 stored [e][t] for coalesced MLP reads

// Packed f32x2 helpers (Blackwell FFMA2 path — PTX only)
__device__ __forceinline__ unsigned long long mul2(unsigned long long a, unsigned long long b) {
    unsigned long long r;
    asm("mul.rn.f32x2 %0, %1, %2;" : "=l"(r) : "l"(a), "l"(b));
    return r;
}
__device__ __forceinline__ unsigned long long fma2(unsigned long long a, unsigned long long b, unsigned long long c) {
    unsigned long long r;
    asm("fma.rn.f32x2 %0, %1, %2, %3;" : "=l"(r) : "l"(a), "l"(b), "l"(c));
    return r;
}
__device__ __forceinline__ float hsum2(unsigned long long v) {
    float a, b;
    asm("mov.b64 {%0, %1}, %2;" : "=f"(a), "=f"(b) : "l"(v));
    return a + b;
}

// ---------------------------------------------------------------------------
// Cosine kernel, 2 pairs in flight per warp.
// Warp handles edge e at times (tt, tt+4) simultaneously: same src/dst -> one
// edge fetch, 32 gather LDGs issued together (2x memory-level parallelism),
// and the two reduction chains interleave to hide SHFL latency.
// Lane layout: quarter (lane>>3) = head m; lane&7 = 16-float d-chunk.
// Outer loop over tt keeps the concurrent L2 working set at 2 t-slices
// (102 MB < 126 MB L2).
// int64-vs-int32 edge dtype detected inline per warp (values < 100000 => for
// int64 inputs every odd 32-bit word of the first 8 entries is zero).
// ---------------------------------------------------------------------------
__global__ void __launch_bounds__(256) cos_kernel(const void* __restrict__ el,
                                                  const float* __restrict__ z1,
                                                  const float* __restrict__ w1) {
    const int lane = threadIdx.x & 31;
    const int m    = lane >> 3;     // head index 0..3
    const int dg   = lane & 7;      // d-chunk 0..7 (16 floats each)
    const int gw   = (int)((blockIdx.x * blockDim.x + threadIdx.x) >> 5);
    const int nw   = (int)((gridDim.x * blockDim.x) >> 5);

    // Inline dtype detection (uniform across warp; branch is warp-uniform)
    const int* ew = (const int*)el;
    int is64 = 1;
#pragma unroll
    for (int i = 1; i < 16; i += 2) is64 &= (ew[i] == 0);

    // Hoist w^2 for this lane's (m, d-chunk): 8 packed f32x2 values
    unsigned long long w2p[8];
    {
        const ulonglong2* wp = (const ulonglong2*)(w1 + m * DD + dg * 16);
#pragma unroll
        for (int i = 0; i < 4; i++) {
            ulonglong2 w = __ldg(wp + i);
            w2p[2 * i]     = mul2(w.x, w.x);
            w2p[2 * i + 1] = mul2(w.y, w.y);
        }
    }

#pragma unroll 1
    for (int tt = 0; tt < 4; tt++) {
        const float* zA = z1 + (size_t)tt * NN * DD;        // slice tt
        const float* zB = z1 + (size_t)(tt + 4) * NN * DD;  // slice tt+4

#pragma unroll 1
        for (int e = gw; e < EE; e += nw) {
            int src, dst;
            if (is64) {
                longlong2 v = __ldg((const longlong2*)el + e);
                src = (int)v.x; dst = (int)v.y;
            } else {
                int2 v = __ldg((const int2*)el + e);
                src = v.x; dst = v.y;
            }

            const unsigned os = (unsigned)src * DD + (unsigned)dg * 16;
            const unsigned od = (unsigned)dst * DD + (unsigned)dg * 16;
            const ulonglong2* a0p = (const ulonglong2*)(zA + os);
            const ulonglong2* b0p = (const ulonglong2*)(zA + od);
            const ulonglong2* a1p = (const ulonglong2*)(zB + os);
            const ulonglong2* b1p = (const ulonglong2*)(zB + od);

            // Issue all 32 gather loads (2 pairs) before consuming any
            ulonglong2 A0[4], B0[4], A1[4], B1[4];
#pragma unroll
            for (int i = 0; i < 4; i++) {
                A0[i] = __ldg(a0p + i);
                B0[i] = __ldg(b0p + i);
                A1[i] = __ldg(a1p + i);
                B1[i] = __ldg(b1p + i);
            }

            unsigned long long d0 = 0ull, na0 = 0ull, nb0 = 0ull;
            unsigned long long d1 = 0ull, na1 = 0ull, nb1 = 0ull;
#pragma unroll
            for (int i = 0; i < 4; i++) {
                d0  = fma2(mul2(A0[i].x, B0[i].x), w2p[2 * i], d0);
                na0 = fma2(mul2(A0[i].x, A0[i].x), w2p[2 * i], na0);
                nb0 = fma2(mul2(B0[i].x, B0[i].x), w2p[2 * i], nb0);
                d0  = fma2(mul2(A0[i].y, B0[i].y), w2p[2 * i + 1], d0);
                na0 = fma2(mul2(A0[i].y, A0[i].y), w2p[2 * i + 1], na0);
                nb0 = fma2(mul2(B0[i].y, B0[i].y), w2p[2 * i + 1], nb0);

                d1  = fma2(mul2(A1[i].x, B1[i].x), w2p[2 * i], d1);
                na1 = fma2(mul2(A1[i].x, A1[i].x), w2p[2 * i], na1);
                nb1 = fma2(mul2(B1[i].x, B1[i].x), w2p[2 * i], nb1);
                d1  = fma2(mul2(A1[i].y, B1[i].y), w2p[2 * i + 1], d1);
                na1 = fma2(mul2(A1[i].y, A1[i].y), w2p[2 * i + 1], na1);
                nb1 = fma2(mul2(B1[i].y, B1[i].y), w2p[2 * i + 1], nb1);
            }

            float dot0 = hsum2(d0), sa0 = hsum2(na0), sb0 = hsum2(nb0);
            float dot1 = hsum2(d1), sa1 = hsum2(na1), sb1 = hsum2(nb1);

            // Interleaved quarter reductions (xor 1,2,4 stays inside quarter);
            // the two pairs' chains overlap each other's SHFL latency.
#pragma unroll
            for (int ofs = 1; ofs <= 4; ofs <<= 1) {
                dot0 += __shfl_xor_sync(0xffffffffu, dot0, ofs);
                dot1 += __shfl_xor_sync(0xffffffffu, dot1, ofs);
                sa0  += __shfl_xor_sync(0xffffffffu, sa0,  ofs);
                sa1  += __shfl_xor_sync(0xffffffffu, sa1,  ofs);
                sb0  += __shfl_xor_sync(0xffffffffu, sb0,  ofs);
                sb1  += __shfl_xor_sync(0xffffffffu, sb1,  ofs);
            }

            // max(sqrt(x), 1e-8) == sqrt(max(x, 1e-16)) for x >= 0
            float c0 = dot0 * rsqrtf(fmaxf(sa0, 1e-16f) * fmaxf(sb0, 1e-16f));
            float c1 = dot1 * rsqrtf(fmaxf(sa1, 1e-16f) * fmaxf(sb1, 1e-16f));

            // Mean over 4 heads (sum across quarters)
            c0 += __shfl_xor_sync(0xffffffffu, c0, 8);
            c1 += __shfl_xor_sync(0xffffffffu, c1, 8);
            c0 += __shfl_xor_sync(0xffffffffu, c0, 16);
            c1 += __shfl_xor_sync(0xffffffffu, c1, 16);

            if (lane == 0) {
                g_sim[e * TT + tt]     = 0.25f * c0;
                g_sim[e * TT + tt + 4] = 0.25f * c1;
            }
        }
    }
}

// ---------------------------------------------------------------------------
// MLP kernel: one thread per edge. Weights staged in shared memory
// (uniform-address broadcast LDS.128), h0[64] lives in registers.
// ---------------------------------------------------------------------------
__global__ void __launch_bounds__(256) mlp_kernel(const float* __restrict__ W0,
                                                  const float* __restrict__ b0,
                                                  const float* __restrict__ W1,
                                                  const float* __restrict__ b1,
                                                  const float* __restrict__ Wp,
                                                  const float* __restrict__ bp,
                                                  float* __restrict__ out) {
    __shared__ float sW0[HH0 * TT];      // 512
    __shared__ float sb0[HH0];
    __shared__ float sW1[HH1 * HH0];     // 2048
    __shared__ float sb1[HH1];
    __shared__ float sWp[HH1];
    __shared__ float sbp;

    const int tid = threadIdx.x;
    for (int i = tid; i < HH0 * TT; i += 256) sW0[i] = W0[i];
    for (int i = tid; i < HH1 * HH0; i += 256) sW1[i] = W1[i];
    if (tid < HH0) sb0[tid] = b0[tid];
    if (tid < HH1) { sb1[tid] = b1[tid]; sWp[tid] = Wp[tid]; }
    if (tid == 0) sbp = bp[0];
    __syncthreads();

    const int e = blockIdx.x * 256 + tid;
    if (e >= EE) return;

    float s[8];
    *(float4*)(s)     = *(const float4*)(g_sim + e * 8);
    *(float4*)(s + 4) = *(const float4*)(g_sim + e * 8 + 4);

    float h0[HH0];
#pragma unroll
    for (int j = 0; j < HH0; j++) {
        const float4* w = (const float4*)(sW0 + j * TT);
        float4 wa = w[0], wb = w[1];
        float acc = sb0[j];
        acc += s[0] * wa.x + s[1] * wa.y + s[2] * wa.z + s[3] * wa.w;
        acc += s[4] * wb.x + s[5] * wb.y + s[6] * wb.z + s[7] * wb.w;
        h0[j] = fmaxf(acc, 0.0f);
    }

    float pred = sbp;
    for (int k = 0; k < HH1; k++) {
        float acc = sb1[k];
        const float4* w = (const float4*)(sW1 + k * HH0);
#pragma unroll
        for (int j = 0; j < HH0 / 4; j++) {
            float4 ww = w[j];
            acc += h0[4 * j]     * ww.x + h0[4 * j + 1] * ww.y +
                   h0[4 * j + 2] * ww.z + h0[4 * j + 3] * ww.w;
        }
        pred += fmaxf(acc, 0.0f) * sWp[k];
    }
    out[e] = pred;
}

// ---------------------------------------------------------------------------
// Launch: fused gather/cosine (dtype detection inline) -> tiny MLP.
// Input order (metadata): edge_list, z1_trains, z2_trains(unused),
// weight_vec1, weight_vec2(unused), W0, b0, W1, b1, Wp, bp
// ---------------------------------------------------------------------------
extern "C" void kernel_launch(void* const* d_in, const int* in_sizes, int n_in,
                              void* d_out, int out_size) {
    const void*  edge = d_in[0];
    const float* z1   = (const float*)d_in[1];
    const float* w1   = (const float*)d_in[3];
    const float* W0   = (const float*)d_in[5];
    const float* b0   = (const float*)d_in[6];
    const float* W1   = (const float*)d_in[7];
    const float* b1   = (const float*)d_in[8];
    const float* Wp   = (const float*)d_in[9];
    const float* bp   = (const float*)d_in[10];

    cos_kernel<<<1184, 256>>>(edge, z1, w1);
    mlp_kernel<<<(EE + 255) / 256, 256>>>(W0, b0, W1, b1, Wp, bp, (float*)d_out);
}

// round 5
// speedup vs baseline: 1.0031x; 1.0031x over previous
#include <cuda_runtime.h>
#include <cstdint>

// Problem constants
#define TT   8
#define NN   100000
#define DD   128
#define EE   50000
#define HH0  64
#define HH1  32

// Scratch (allocation-free rule: __device__ globals)
__device__ float g_sim[EE * TT];   // s1 stored [e][t] for coalesced MLP reads

// Packed f32x2 helpers (Blackwell FFMA2 path — PTX only)
__device__ __forceinline__ unsigned long long mul2(unsigned long long a, unsigned long long b) {
    unsigned long long r;
    asm("mul.rn.f32x2 %0, %1, %2;" : "=l"(r) : "l"(a), "l"(b));
    return r;
}
__device__ __forceinline__ unsigned long long fma2(unsigned long long a, unsigned long long b, unsigned long long c) {
    unsigned long long r;
    asm("fma.rn.f32x2 %0, %1, %2, %3;" : "=l"(r) : "l"(a), "l"(b), "l"(c));
    return r;
}
__device__ __forceinline__ float hsum2(unsigned long long v) {
    float a, b;
    asm("mov.b64 {%0, %1}, %2;" : "=f"(a), "=f"(b) : "l"(v));
    return a + b;
}

// ---------------------------------------------------------------------------
// Cosine kernel, 2 pairs in flight per warp.
// Warp handles edge e at times (tt, tt+4) simultaneously: same src/dst -> one
// edge fetch, 32 gather LDGs issued together (2x memory-level parallelism),
// and the two reduction chains interleave to hide SHFL latency.
// Lane layout: quarter (lane>>3) = head m; lane&7 = 16-float d-chunk.
// Outer loop over tt keeps the concurrent L2 working set at 2 t-slices
// (102 MB < 126 MB L2).
// int64-vs-int32 edge dtype detected inline per warp (values < 100000 => for
// int64 inputs every odd 32-bit word of the first 8 entries is zero).
// ---------------------------------------------------------------------------
__global__ void __launch_bounds__(256) cos_kernel(const void* __restrict__ el,
                                                  const float* __restrict__ z1,
                                                  const float* __restrict__ w1) {
    const int lane = threadIdx.x & 31;
    const int m    = lane >> 3;     // head index 0..3
    const int dg   = lane & 7;      // d-chunk 0..7 (16 floats each)
    const int gw   = (int)((blockIdx.x * blockDim.x + threadIdx.x) >> 5);
    const int nw   = (int)((gridDim.x * blockDim.x) >> 5);

    // Inline dtype detection (uniform across warp; branch is warp-uniform)
    const int* ew = (const int*)el;
    int is64 = 1;
#pragma unroll
    for (int i = 1; i < 16; i += 2) is64 &= (ew[i] == 0);

    // Hoist w^2 for this lane's (m, d-chunk): 8 packed f32x2 values
    unsigned long long w2p[8];
    {
        const ulonglong2* wp = (const ulonglong2*)(w1 + m * DD + dg * 16);
#pragma unroll
        for (int i = 0; i < 4; i++) {
            ulonglong2 w = __ldg(wp + i);
            w2p[2 * i]     = mul2(w.x, w.x);
            w2p[2 * i + 1] = mul2(w.y, w.y);
        }
    }

#pragma unroll 1
    for (int tt = 0; tt < 4; tt++) {
        const float* zA = z1 + (size_t)tt * NN * DD;        // slice tt
        const float* zB = z1 + (size_t)(tt + 4) * NN * DD;  // slice tt+4

#pragma unroll 1
        for (int e = gw; e < EE; e += nw) {
            int src, dst;
            if (is64) {
                longlong2 v = __ldg((const longlong2*)el + e);
                src = (int)v.x; dst = (int)v.y;
            } else {
                int2 v = __ldg((const int2*)el + e);
                src = v.x; dst = v.y;
            }

            const unsigned os = (unsigned)src * DD + (unsigned)dg * 16;
            const unsigned od = (unsigned)dst * DD + (unsigned)dg * 16;
            const ulonglong2* a0p = (const ulonglong2*)(zA + os);
            const ulonglong2* b0p = (const ulonglong2*)(zA + od);
            const ulonglong2* a1p = (const ulonglong2*)(zB + os);
            const ulonglong2* b1p = (const ulonglong2*)(zB + od);

            // Issue all 32 gather loads (2 pairs) before consuming any
            ulonglong2 A0[4], B0[4], A1[4], B1[4];
#pragma unroll
            for (int i = 0; i < 4; i++) {
                A0[i] = __ldg(a0p + i);
                B0[i] = __ldg(b0p + i);
                A1[i] = __ldg(a1p + i);
                B1[i] = __ldg(b1p + i);
            }

            unsigned long long d0 = 0ull, na0 = 0ull, nb0 = 0ull;
            unsigned long long d1 = 0ull, na1 = 0ull, nb1 = 0ull;
#pragma unroll
            for (int i = 0; i < 4; i++) {
                d0  = fma2(mul2(A0[i].x, B0[i].x), w2p[2 * i], d0);
                na0 = fma2(mul2(A0[i].x, A0[i].x), w2p[2 * i], na0);
                nb0 = fma2(mul2(B0[i].x, B0[i].x), w2p[2 * i], nb0);
                d0  = fma2(mul2(A0[i].y, B0[i].y), w2p[2 * i + 1], d0);
                na0 = fma2(mul2(A0[i].y, A0[i].y), w2p[2 * i + 1], na0);
                nb0 = fma2(mul2(B0[i].y, B0[i].y), w2p[2 * i + 1], nb0);

                d1  = fma2(mul2(A1[i].x, B1[i].x), w2p[2 * i], d1);
                na1 = fma2(mul2(A1[i].x, A1[i].x), w2p[2 * i], na1);
                nb1 = fma2(mul2(B1[i].x, B1[i].x), w2p[2 * i], nb1);
                d1  = fma2(mul2(A1[i].y, B1[i].y), w2p[2 * i + 1], d1);
                na1 = fma2(mul2(A1[i].y, A1[i].y), w2p[2 * i + 1], na1);
                nb1 = fma2(mul2(B1[i].y, B1[i].y), w2p[2 * i + 1], nb1);
            }

            float dot0 = hsum2(d0), sa0 = hsum2(na0), sb0 = hsum2(nb0);
            float dot1 = hsum2(d1), sa1 = hsum2(na1), sb1 = hsum2(nb1);

            // Interleaved quarter reductions (xor 1,2,4 stays inside quarter);
            // the two pairs' chains overlap each other's SHFL latency.
#pragma unroll
            for (int ofs = 1; ofs <= 4; ofs <<= 1) {
                dot0 += __shfl_xor_sync(0xffffffffu, dot0, ofs);
                dot1 += __shfl_xor_sync(0xffffffffu, dot1, ofs);
                sa0  += __shfl_xor_sync(0xffffffffu, sa0,  ofs);
                sa1  += __shfl_xor_sync(0xffffffffu, sa1,  ofs);
                sb0  += __shfl_xor_sync(0xffffffffu, sb0,  ofs);
                sb1  += __shfl_xor_sync(0xffffffffu, sb1,  ofs);
            }

            // max(sqrt(x), 1e-8) == sqrt(max(x, 1e-16)) for x >= 0
            float c0 = dot0 * rsqrtf(fmaxf(sa0, 1e-16f) * fmaxf(sb0, 1e-16f));
            float c1 = dot1 * rsqrtf(fmaxf(sa1, 1e-16f) * fmaxf(sb1, 1e-16f));

            // Mean over 4 heads (sum across quarters)
            c0 += __shfl_xor_sync(0xffffffffu, c0, 8);
            c1 += __shfl_xor_sync(0xffffffffu, c1, 8);
            c0 += __shfl_xor_sync(0xffffffffu, c0, 16);
            c1 += __shfl_xor_sync(0xffffffffu, c1, 16);

            if (lane == 0) {
                g_sim[e * TT + tt]     = 0.25f * c0;
                g_sim[e * TT + tt + 4] = 0.25f * c1;
            }
        }
    }
}

// ---------------------------------------------------------------------------
// MLP kernel: one thread per edge. Weights staged in shared memory
// (uniform-address broadcast LDS.128), h0[64] lives in registers.
// ---------------------------------------------------------------------------
__global__ void __launch_bounds__(256) mlp_kernel(const float* __restrict__ W0,
                                                  const float* __restrict__ b0,
                                                  const float* __restrict__ W1,
                                                  const float* __restrict__ b1,
                                                  const float* __restrict__ Wp,
                                                  const float* __restrict__ bp,
                                                  float* __restrict__ out) {
    __shared__ float sW0[HH0 * TT];      // 512
    __shared__ float sb0[HH0];
    __shared__ float sW1[HH1 * HH0];     // 2048
    __shared__ float sb1[HH1];
    __shared__ float sWp[HH1];
    __shared__ float sbp;

    const int tid = threadIdx.x;
    for (int i = tid; i < HH0 * TT; i += 256) sW0[i] = W0[i];
    for (int i = tid; i < HH1 * HH0; i += 256) sW1[i] = W1[i];
    if (tid < HH0) sb0[tid] = b0[tid];
    if (tid < HH1) { sb1[tid] = b1[tid]; sWp[tid] = Wp[tid]; }
    if (tid == 0) sbp = bp[0];
    __syncthreads();

    const int e = blockIdx.x * 256 + tid;
    if (e >= EE) return;

    float s[8];
    *(float4*)(s)     = *(const float4*)(g_sim + e * 8);
    *(float4*)(s + 4) = *(const float4*)(g_sim + e * 8 + 4);

    float h0[HH0];
#pragma unroll
    for (int j = 0; j < HH0; j++) {
        const float4* w = (const float4*)(sW0 + j * TT);
        float4 wa = w[0], wb = w[1];
        float acc = sb0[j];
        acc += s[0] * wa.x + s[1] * wa.y + s[2] * wa.z + s[3] * wa.w;
        acc += s[4] * wb.x + s[5] * wb.y + s[6] * wb.z + s[7] * wb.w;
        h0[j] = fmaxf(acc, 0.0f);
    }

    float pred = sbp;
    for (int k = 0; k < HH1; k++) {
        float acc = sb1[k];
        const float4* w = (const float4*)(sW1 + k * HH0);
#pragma unroll
        for (int j = 0; j < HH0 / 4; j++) {
            float4 ww = w[j];
            acc += h0[4 * j]     * ww.x + h0[4 * j + 1] * ww.y +
                   h0[4 * j + 2] * ww.z + h0[4 * j + 3] * ww.w;
        }
        pred += fmaxf(acc, 0.0f) * sWp[k];
    }
    out[e] = pred;
}

// ---------------------------------------------------------------------------
// Launch: fused gather/cosine (dtype detection inline) -> tiny MLP.
// Input order (metadata): edge_list, z1_trains, z2_trains(unused),
// weight_vec1, weight_vec2(unused), W0, b0, W1, b1, Wp, bp
// ---------------------------------------------------------------------------
extern "C" void kernel_launch(void* const* d_in, const int* in_sizes, int n_in,
                              void* d_out, int out_size) {
    const void*  edge = d_in[0];
    const float* z1   = (const float*)d_in[1];
    const float* w1   = (const float*)d_in[3];
    const float* W0   = (const float*)d_in[5];
    const float* b0   = (const float*)d_in[6];
    const float* W1   = (const float*)d_in[7];
    const float* b1   = (const float*)d_in[8];
    const float* Wp   = (const float*)d_in[9];
    const float* bp   = (const float*)d_in[10];

    cos_kernel<<<1184, 256>>>(edge, z1, w1);
    mlp_kernel<<<(EE + 255) / 256, 256>>>(W0, b0, W1, b1, Wp, bp, (float*)d_out);
}

// round 7
// speedup vs baseline: 2.1342x; 2.1276x over previous
#include <cuda_runtime.h>
#include <cstdint>

// Problem constants
#define TT   8
#define NN   100000
#define DD   128
#define EE   50000
#define HH0  64
#define HH1  32

// cos pipeline config
#define CWARPS 4          // warps per block
#define SLOTS  4          // smem slots per warp
#define PD     3          // prefetch distance (cp.async groups in flight)
#define STAGE_FLOATS 512  // 4 rows x 128 floats
#define STAGE_BYTES  2048

__device__ float g_sim[EE * TT];   // s1 stored [e][t] for coalesced MLP reads

// Packed f32x2 helpers (Blackwell FFMA2 path — PTX only)
__device__ __forceinline__ unsigned long long mul2(unsigned long long a, unsigned long long b) {
    unsigned long long r;
    asm("mul.rn.f32x2 %0, %1, %2;" : "=l"(r) : "l"(a), "l"(b));
    return r;
}
__device__ __forceinline__ unsigned long long fma2(unsigned long long a, unsigned long long b, unsigned long long c) {
    unsigned long long r;
    asm("fma.rn.f32x2 %0, %1, %2, %3;" : "=l"(r) : "l"(a), "l"(b), "l"(c));
    return r;
}
__device__ __forceinline__ float hsum2(unsigned long long v) {
    float a, b;
    asm("mov.b64 {%0, %1}, %2;" : "=f"(a), "=f"(b) : "l"(v));
    return a + b;
}
__device__ __forceinline__ unsigned long long pack2(float lo, float hi) {
    unsigned long long r;
    asm("mov.b64 %0, {%1, %2};" : "=l"(r) : "f"(lo), "f"(hi));
    return r;
}

// 16B-chunk swizzle within a 512B row: position(q) = q ^ (q>>3).
// Global chunk q is STORED at smem position swz16(q); readers fetch chunk q
// from position swz16(q). Makes the (m,dg)-layout reads (8 distinct addresses
// at 64B stride, 4-way replicated) conflict-free.
__device__ __forceinline__ unsigned swz16(unsigned q) { return q ^ (q >> 3); }

// ---------------------------------------------------------------------------
// Cosine kernel with cp.async pipeline.
// One warp per (tp, e) work item handling times (tp, tp+4): 4 gathered rows
// (a0,b0,a1,b1) = 2KB per item. Warp owns SLOTS=4 smem slots and prefetches
// PD=3 items ahead via cp.async.cg (16B/lane, 4 instrs/item), so gather
// latency never touches the register scoreboard. Edge indices are themselves
// prefetched through a 2-deep register ring.
// ---------------------------------------------------------------------------
__global__ void __launch_bounds__(CWARPS * 32) cos_kernel(const void* __restrict__ el,
                                                          const float* __restrict__ z1,
                                                          const float* __restrict__ w1) {
    __shared__ float sbuf[CWARPS][SLOTS][STAGE_FLOATS];

    const int lane = threadIdx.x & 31;
    const int wid  = threadIdx.x >> 5;
    const int m    = lane >> 3;     // head index 0..3
    const int dg   = lane & 7;      // d-chunk 0..7 (16 floats each)
    const int gw   = (int)((blockIdx.x * blockDim.x + threadIdx.x) >> 5);
    const int nw   = (int)((gridDim.x * blockDim.x) >> 5);
    const int TOTAL = 4 * EE;

    // Inline int64-vs-int32 edge dtype detection (warp-uniform; indices
    // < 100000 => for int64 every odd 32-bit word is zero)
    const int* ew = (const int*)el;
    int is64 = 1;
#pragma unroll
    for (int i = 1; i < 16; i += 2) is64 &= (ew[i] == 0);

    // Hoist w^2 for this lane's (m, d-chunk): 8 packed f32x2 values
    unsigned long long w2p[8];
    {
        const ulonglong2* wp = (const ulonglong2*)(w1 + m * DD + dg * 16);
#pragma unroll
        for (int i = 0; i < 4; i++) {
            ulonglong2 w = __ldg(wp + i);
            w2p[2 * i]     = mul2(w.x, w.x);
            w2p[2 * i + 1] = mul2(w.y, w.y);
        }
    }

    // Read offsets: global chunk (dg*4+c) lives at smem position swz16(.)
    unsigned roff[4];
#pragma unroll
    for (int c = 0; c < 4; c++) roff[c] = swz16((unsigned)dg * 4 + c) * 16;

    // cp.async: lane copies GLOBAL chunk `lane` (offset lane*16) into smem
    // position swz16(lane). Source unswizzled, destination swizzled.
    const unsigned goff = (unsigned)lane * 16;        // global byte offset
    const unsigned woff = swz16((unsigned)lane) * 16; // smem byte offset

    const unsigned sbase = (unsigned)__cvta_generic_to_shared(&sbuf[wid][0][0]);

    // --- helpers -----------------------------------------------------------
    auto loadEdge = [&](int j) -> int2 {
        int jc = j < TOTAL ? j : TOTAL - 1;
        int e  = jc % EE;
        int2 r;
        if (is64) {
            longlong2 v = __ldg((const longlong2*)el + e);
            r.x = (int)v.x; r.y = (int)v.y;
        } else {
            r = __ldg((const int2*)el + e);
        }
        return r;
    };

    auto prefetch = [&](int j, int2 ed, int slot) {
        if (j < TOTAL) {
            int tp = j / EE;
            const char* zA = (const char*)z1 + (size_t)tp * NN * 512;
            const char* zB = zA + (size_t)4 * NN * 512;
            const char* g0 = zA + (size_t)(unsigned)ed.x * 512 + goff;
            const char* g1 = zA + (size_t)(unsigned)ed.y * 512 + goff;
            const char* g2 = zB + (size_t)(unsigned)ed.x * 512 + goff;
            const char* g3 = zB + (size_t)(unsigned)ed.y * 512 + goff;
            unsigned sm = sbase + (unsigned)slot * STAGE_BYTES + woff;
            asm volatile("cp.async.cg.shared.global [%0], [%1], 16;\n" :: "r"(sm),        "l"(g0));
            asm volatile("cp.async.cg.shared.global [%0], [%1], 16;\n" :: "r"(sm + 512),  "l"(g1));
            asm volatile("cp.async.cg.shared.global [%0], [%1], 16;\n" :: "r"(sm + 1024), "l"(g2));
            asm volatile("cp.async.cg.shared.global [%0], [%1], 16;\n" :: "r"(sm + 1536), "l"(g3));
        }
        asm volatile("cp.async.commit_group;\n");  // empty group OK when guarded out
    };
    // ------------------------------------------------------------------------

    // Prologue: PD groups in flight + edge register ring 2 iterations deep
    prefetch(gw,          loadEdge(gw),          0);
    prefetch(gw + nw,     loadEdge(gw + nw),     1);
    prefetch(gw + 2 * nw, loadEdge(gw + 2 * nw), 2);
    int2 ering[2];
    ering[0] = loadEdge(gw + 3 * nw);
    ering[1] = loadEdge(gw + 4 * nw);

    int cnt = 0;
#pragma unroll 1
    for (int j = gw; j < TOTAL; j += nw, cnt++) {
        asm volatile("cp.async.wait_group %0;\n" :: "n"(PD - 1));
        __syncwarp();

        const int slot = cnt & (SLOTS - 1);
        const char* st = (const char*)&sbuf[wid][slot][0];

        // ---- compute both pairs from smem ----
        unsigned long long d0 = 0ull, na0 = 0ull, nb0 = 0ull;
        unsigned long long d1 = 0ull, na1 = 0ull, nb1 = 0ull;
#pragma unroll
        for (int c = 0; c < 4; c++) {
            ulonglong2 a0 = *(const ulonglong2*)(st +        roff[c]);
            ulonglong2 b0 = *(const ulonglong2*)(st + 512  + roff[c]);
            ulonglong2 a1 = *(const ulonglong2*)(st + 1024 + roff[c]);
            ulonglong2 b1 = *(const ulonglong2*)(st + 1536 + roff[c]);

            d0  = fma2(mul2(a0.x, b0.x), w2p[2 * c],     d0);
            na0 = fma2(mul2(a0.x, a0.x), w2p[2 * c],     na0);
            nb0 = fma2(mul2(b0.x, b0.x), w2p[2 * c],     nb0);
            d0  = fma2(mul2(a0.y, b0.y), w2p[2 * c + 1], d0);
            na0 = fma2(mul2(a0.y, a0.y), w2p[2 * c + 1], na0);
            nb0 = fma2(mul2(b0.y, b0.y), w2p[2 * c + 1], nb0);

            d1  = fma2(mul2(a1.x, b1.x), w2p[2 * c],     d1);
            na1 = fma2(mul2(a1.x, a1.x), w2p[2 * c],     na1);
            nb1 = fma2(mul2(b1.x, b1.x), w2p[2 * c],     nb1);
            d1  = fma2(mul2(a1.y, b1.y), w2p[2 * c + 1], d1);
            na1 = fma2(mul2(a1.y, a1.y), w2p[2 * c + 1], na1);
            nb1 = fma2(mul2(b1.y, b1.y), w2p[2 * c + 1], nb1);
        }

        // Prefetch next stage NOW (before the shuffle tail) so the LDGSTS
        // issue overlaps the reduction latency.
        prefetch(j + PD * nw, ering[cnt & 1], (cnt + PD) & (SLOTS - 1));
        ering[cnt & 1] = loadEdge(j + 5 * nw);

        float dot0 = hsum2(d0), sa0 = hsum2(na0), sb0 = hsum2(nb0);
        float dot1 = hsum2(d1), sa1 = hsum2(na1), sb1 = hsum2(nb1);

#pragma unroll
        for (int ofs = 1; ofs <= 4; ofs <<= 1) {
            dot0 += __shfl_xor_sync(0xffffffffu, dot0, ofs);
            dot1 += __shfl_xor_sync(0xffffffffu, dot1, ofs);
            sa0  += __shfl_xor_sync(0xffffffffu, sa0,  ofs);
            sa1  += __shfl_xor_sync(0xffffffffu, sa1,  ofs);
            sb0  += __shfl_xor_sync(0xffffffffu, sb0,  ofs);
            sb1  += __shfl_xor_sync(0xffffffffu, sb1,  ofs);
        }

        // max(sqrt(x), 1e-8) == sqrt(max(x, 1e-16)) for x >= 0
        float c0 = dot0 * rsqrtf(fmaxf(sa0, 1e-16f) * fmaxf(sb0, 1e-16f));
        float c1 = dot1 * rsqrtf(fmaxf(sa1, 1e-16f) * fmaxf(sb1, 1e-16f));

        c0 += __shfl_xor_sync(0xffffffffu, c0, 8);
        c1 += __shfl_xor_sync(0xffffffffu, c1, 8);
        c0 += __shfl_xor_sync(0xffffffffu, c0, 16);
        c1 += __shfl_xor_sync(0xffffffffu, c1, 16);

        if (lane == 0) {
            int tp = j / EE;
            int e  = j - tp * EE;
            g_sim[e * TT + tp]     = 0.25f * c0;
            g_sim[e * TT + tp + 4] = 0.25f * c1;
        }
    }
}

// ---------------------------------------------------------------------------
// MLP kernel: one thread per edge, acc-outer formulation with packed f32x2.
// No h0[64] register array: for each hidden-0 unit j we compute h0_j and
// immediately fold it into the 32 h1 accumulators (16 packed regs) through
// a transposed-W1 smem tile (uniform-address LDS.128 broadcast).
// ---------------------------------------------------------------------------
__global__ void __launch_bounds__(256) mlp_kernel(const float* __restrict__ W0,
                                                  const float* __restrict__ b0,
                                                  const float* __restrict__ W1,
                                                  const float* __restrict__ b1,
                                                  const float* __restrict__ Wp,
                                                  const float* __restrict__ bp,
                                                  float* __restrict__ out) {
    __shared__ float sW0[HH0 * TT];        // 512
    __shared__ float sb0[HH0];
    __shared__ float sW1t[HH0 * HH1];      // transposed: [j][k]
    __shared__ float sb1[HH1];
    __shared__ float sWp[HH1];
    __shared__ float sbp;

    const int tid = threadIdx.x;
    for (int i = tid; i < HH0 * TT; i += 256) sW0[i] = W0[i];
    for (int i = tid; i < HH1 * HH0; i += 256) {
        int k = i / HH0, j = i - k * HH0;          // W1 is [k][j]
        sW1t[j * HH1 + k] = W1[i];
    }
    if (tid < HH0) sb0[tid] = b0[tid];
    if (tid < HH1) { sb1[tid] = b1[tid]; sWp[tid] = Wp[tid]; }
    if (tid == 0) sbp = bp[0];
    __syncthreads();

    const int e = blockIdx.x * 256 + tid;
    if (e >= EE) return;

    // sims for this edge, packed
    ulonglong2 sv0 = *(const ulonglong2*)(g_sim + e * 8);
    ulonglong2 sv1 = *(const ulonglong2*)(g_sim + e * 8 + 4);

    unsigned long long acc2[HH1 / 2];
#pragma unroll
    for (int k = 0; k < HH1 / 2; k++) acc2[k] = ((const unsigned long long*)sb1)[k];

#pragma unroll
    for (int j = 0; j < HH0; j++) {
        const ulonglong2* w = (const ulonglong2*)(sW0 + j * TT);
        ulonglong2 w0 = w[0], w1v = w[1];
        unsigned long long t = mul2(sv0.x, w0.x);
        t = fma2(sv0.y, w0.y, t);
        t = fma2(sv1.x, w1v.x, t);
        t = fma2(sv1.y, w1v.y, t);
        float h = fmaxf(hsum2(t) + sb0[j], 0.0f);
        unsigned long long h2 = pack2(h, h);

        const ulonglong2* wr = (const ulonglong2*)(sW1t + j * HH1);
#pragma unroll
        for (int k2 = 0; k2 < HH1 / 4; k2++) {
            ulonglong2 wv = wr[k2];
            acc2[2 * k2]     = fma2(h2, wv.x, acc2[2 * k2]);
            acc2[2 * k2 + 1] = fma2(h2, wv.y, acc2[2 * k2 + 1]);
        }
    }

    float pred = sbp;
#pragma unroll
    for (int k = 0; k < HH1 / 2; k++) {
        float x, y;
        asm("mov.b64 {%0, %1}, %2;" : "=f"(x), "=f"(y) : "l"(acc2[k]));
        pred += fmaxf(x, 0.0f) * sWp[2 * k] + fmaxf(y, 0.0f) * sWp[2 * k + 1];
    }
    out[e] = pred;
}

// ---------------------------------------------------------------------------
// Launch. Input order (metadata): edge_list, z1_trains, z2_trains(unused),
// weight_vec1, weight_vec2(unused), W0, b0, W1, b1, Wp, bp
// ---------------------------------------------------------------------------
extern "C" void kernel_launch(void* const* d_in, const int* in_sizes, int n_in,
                              void* d_out, int out_size) {
    const void*  edge = d_in[0];
    const float* z1   = (const float*)d_in[1];
    const float* w1   = (const float*)d_in[3];
    const float* W0   = (const float*)d_in[5];
    const float* b0   = (const float*)d_in[6];
    const float* W1   = (const float*)d_in[7];
    const float* b1   = (const float*)d_in[8];
    const float* Wp   = (const float*)d_in[9];
    const float* bp   = (const float*)d_in[10];

    cos_kernel<<<888, CWARPS * 32>>>(edge, z1, w1);
    mlp_kernel<<<(EE + 255) / 256, 256>>>(W0, b0, W1, b1, Wp, bp, (float*)d_out);
}